// round 7
// baseline (speedup 1.0000x reference)
#include <cuda_runtime.h>
#include <math.h>

#define DD 128
#define NQ_MAX 8192
#define NT_MAX 8192
#define E_MAX  262144

// ---------------- scratch (static device allocations; no cudaMalloc) ----------------
__device__ float g_Xq_ac[NQ_MAX*DD];
__device__ float g_Xt_ac[NT_MAX*DD];
__device__ float g_Xq_vc[NQ_MAX*DD];
__device__ float g_Xt_vc[NT_MAX*DD];
__device__ float g_Xq2t [NT_MAX*DD];
__device__ float g_Xt2q [NQ_MAX*DD];
__device__ float g_Xq_m [NQ_MAX*DD];
__device__ float g_Xt_m [NT_MAX*DD];
__device__ float g_V1q  [NQ_MAX*DD];
__device__ float g_V2q  [NQ_MAX*DD];
__device__ float g_V1t  [NT_MAX*DD];
__device__ float g_V2t  [NT_MAX*DD];
__device__ float g_logits[E_MAX];
__device__ float g_maxq[NQ_MAX];
__device__ float g_sumq[NQ_MAX];
__device__ float g_maxt[NT_MAX];
__device__ float g_sumt[NT_MAX];
__device__ float g_maxd_t[NT_MAX];
__device__ float g_sumd_t[NT_MAX];
__device__ float g_maxd_q[NQ_MAX];
__device__ float g_sumd_q[NQ_MAX];
__device__ float g_sAt[NT_MAX];
__device__ float g_sBt[NT_MAX];
__device__ float g_sAq[NQ_MAX];
__device__ float g_sBq[NQ_MAX];
__device__ float g_qmean[DD];
__device__ float g_bmt[DD];

// ---------------- helpers ----------------
__device__ __forceinline__ void atomicMaxF(float* addr, float v) {
    // monotone bit trick: valid for all non-NaN floats
    if (v >= 0.0f) atomicMax((int*)addr, __float_as_int(v));
    else           atomicMin((unsigned int*)addr, (unsigned int)__float_as_int(v));
}

__global__ void fillf_kernel(float* __restrict__ p, float v, int n) {
    int i = blockIdx.x * blockDim.x + threadIdx.x;
    if (i < n) p[i] = v;
}

// ---------------- GEMM: C[M,128] = concat(A1[M,k1], A2[M,k2]) @ B[K,128] + bias, opt ELU ----------------
__global__ void gemm2_kernel(const float* __restrict__ A1, const float* __restrict__ A2,
                             int k1, int k2,
                             const float* __restrict__ B, const float* __restrict__ bias,
                             float* __restrict__ C, int doElu, int M)
{
    const int K = k1 + k2;
    __shared__ __align__(16) float As[32][33];
    __shared__ __align__(16) float Bs[32][128];
    const int tid = threadIdx.x;
    const int tx = tid & 15;         // col group
    const int ty = tid >> 4;         // row group (2 rows each)
    const int m0 = blockIdx.x * 32;
    if (m0 >= M) return;

    float acc0[8], acc1[8];
#pragma unroll
    for (int j = 0; j < 8; j++) { acc0[j] = 0.f; acc1[j] = 0.f; }

    for (int kk = 0; kk < K; kk += 32) {
#pragma unroll
        for (int i = tid; i < 1024; i += 256) {
            int m = i >> 5, k = i & 31;
            int col = kk + k;
            float v = (col < k1) ? __ldg(&A1[(size_t)(m0 + m) * k1 + col])
                                 : __ldg(&A2[(size_t)(m0 + m) * k2 + (col - k1)]);
            As[k][m] = v;
        }
#pragma unroll
        for (int i = tid; i < 4096; i += 256) {
            int k = i >> 7, n = i & 127;
            Bs[k][n] = __ldg(&B[(size_t)(kk + k) * 128 + n]);
        }
        __syncthreads();
#pragma unroll
        for (int k = 0; k < 32; k++) {
            float a0 = As[k][ty * 2 + 0];
            float a1 = As[k][ty * 2 + 1];
            const float4* bp = reinterpret_cast<const float4*>(&Bs[k][tx * 8]);
            float4 b0 = bp[0], b1 = bp[1];
            acc0[0] += a0 * b0.x; acc0[1] += a0 * b0.y; acc0[2] += a0 * b0.z; acc0[3] += a0 * b0.w;
            acc0[4] += a0 * b1.x; acc0[5] += a0 * b1.y; acc0[6] += a0 * b1.z; acc0[7] += a0 * b1.w;
            acc1[0] += a1 * b0.x; acc1[1] += a1 * b0.y; acc1[2] += a1 * b0.z; acc1[3] += a1 * b0.w;
            acc1[4] += a1 * b1.x; acc1[5] += a1 * b1.y; acc1[6] += a1 * b1.z; acc1[7] += a1 * b1.w;
        }
        __syncthreads();
    }

    const int r0 = m0 + ty * 2;
    const int c0 = tx * 8;
    float bb[8];
#pragma unroll
    for (int j = 0; j < 8; j++) bb[j] = bias ? __ldg(&bias[c0 + j]) : 0.f;
#pragma unroll
    for (int j = 0; j < 8; j++) {
        float v0 = acc0[j] + bb[j];
        float v1 = acc1[j] + bb[j];
        if (doElu) {
            v0 = v0 > 0.f ? v0 : expm1f(v0);
            v1 = v1 > 0.f ? v1 : expm1f(v1);
        }
        acc0[j] = v0; acc1[j] = v1;
    }
    float4* o0 = reinterpret_cast<float4*>(&C[(size_t)r0 * 128 + c0]);
    float4* o1 = reinterpret_cast<float4*>(&C[(size_t)(r0 + 1) * 128 + c0]);
    o0[0] = make_float4(acc0[0], acc0[1], acc0[2], acc0[3]);
    o0[1] = make_float4(acc0[4], acc0[5], acc0[6], acc0[7]);
    o1[0] = make_float4(acc1[0], acc1[1], acc1[2], acc1[3]);
    o1[1] = make_float4(acc1[4], acc1[5], acc1[6], acc1[7]);
}

// ---------------- cross pass1: per-edge 128-d dot + segment max (both seg maps) ----------------
__global__ void cross_dot_max(const int* __restrict__ src, const int* __restrict__ dst,
                              const float* __restrict__ Xa, const float* __restrict__ Xb,
                              float* __restrict__ logits,
                              float* __restrict__ maxs, float* __restrict__ maxd, int E)
{
    int e = (blockIdx.x * blockDim.x + threadIdx.x) >> 5;
    int lane = threadIdx.x & 31;
    if (e >= E) return;
    int s = __ldg(&src[e]), t = __ldg(&dst[e]);
    float4 a = __ldg(&reinterpret_cast<const float4*>(Xa + (size_t)s * 128)[lane]);
    float4 b = __ldg(&reinterpret_cast<const float4*>(Xb + (size_t)t * 128)[lane]);
    float d = a.x * b.x + a.y * b.y + a.z * b.z + a.w * b.w;
#pragma unroll
    for (int off = 16; off > 0; off >>= 1) d += __shfl_down_sync(0xffffffffu, d, off);
    if (lane == 0) {
        logits[e] = d;
        atomicMaxF(&maxs[s], d);
        atomicMaxF(&maxd[t], d);
    }
}

// ---------------- cross pass2: exp-sums for both segmentations ----------------
__global__ void cross_expsum(const int* __restrict__ src, const int* __restrict__ dst,
                             const float* __restrict__ logits,
                             const float* __restrict__ maxs, const float* __restrict__ maxd,
                             float* __restrict__ sums, float* __restrict__ sumd, int E)
{
    int e = blockIdx.x * blockDim.x + threadIdx.x;
    if (e >= E) return;
    float l = logits[e];
    int s = __ldg(&src[e]), t = __ldg(&dst[e]);
    atomicAdd(&sums[s], expf(l - __ldg(&maxs[s])));
    atomicAdd(&sumd[t], expf(l - __ldg(&maxd[t])));
}

// ---------------- intra pass1: logit from per-node scalars + segment max (dst only) ----------------
__global__ void intra_logit_max(const int* __restrict__ src, const int* __restrict__ dst,
                                const float* __restrict__ sA, const float* __restrict__ sB,
                                const float* __restrict__ ba,
                                float* __restrict__ logits, float* __restrict__ maxd, int E)
{
    int e = blockIdx.x * blockDim.x + threadIdx.x;
    if (e >= E) return;
    int t = __ldg(&dst[e]);
    float l = __ldg(&sA[__ldg(&src[e])]) + __ldg(&sB[t]) + __ldg(&ba[0]);
    logits[e] = l;
    atomicMaxF(&maxd[t], l);
}

// ---------------- intra pass2: exp-sum (dst only) ----------------
__global__ void expsum1(const int* __restrict__ dst, const float* __restrict__ logits,
                        const float* __restrict__ maxd, float* __restrict__ sumd, int E)
{
    int e = blockIdx.x * blockDim.x + threadIdx.x;
    if (e >= E) return;
    int t = __ldg(&dst[e]);
    atomicAdd(&sumd[t], expf(logits[e] - __ldg(&maxd[t])));
}

// ---------------- pass3: out[dst] += softmax_weight * V[src] (warp/edge, float atomics) ----------------
__global__ void edge_scatter(const int* __restrict__ src, const int* __restrict__ dst,
                             const float* __restrict__ logits,
                             const float* __restrict__ maxd, const float* __restrict__ sumd,
                             const float* __restrict__ V, float* __restrict__ out, int E)
{
    int e = (blockIdx.x * blockDim.x + threadIdx.x) >> 5;
    int lane = threadIdx.x & 31;
    if (e >= E) return;
    int s = __ldg(&src[e]), t = __ldg(&dst[e]);
    float a = expf(logits[e] - __ldg(&maxd[t])) / __ldg(&sumd[t]);
    float4 v = __ldg(&reinterpret_cast<const float4*>(V + (size_t)s * 128)[lane]);
    float* o = out + (size_t)t * 128 + lane * 4;
    atomicAdd(o + 0, a * v.x);
    atomicAdd(o + 1, a * v.y);
    atomicAdd(o + 2, a * v.z);
    atomicAdd(o + 3, a * v.w);
}

// ---------------- Xt2q shortcut: masked copy ----------------
__global__ void mask_copy(const float* __restrict__ X, const float* __restrict__ sums,
                          float* __restrict__ out, int N)
{
    int i = blockIdx.x * blockDim.x + threadIdx.x;
    if (i >= N * 128) return;
    out[i] = (__ldg(&sums[i >> 7]) > 0.f) ? X[i] : 0.f;
}

// ---------------- per-node scalar dots sA = X.W[0:128], sB = X.W[128:256] ----------------
__global__ void node_scalar(const float* __restrict__ X, const float* __restrict__ Wa,
                            float* __restrict__ sA, float* __restrict__ sB, int N)
{
    int n = (blockIdx.x * blockDim.x + threadIdx.x) >> 5;
    int lane = threadIdx.x & 31;
    if (n >= N) return;
    float4 x  = __ldg(&reinterpret_cast<const float4*>(X + (size_t)n * 128)[lane]);
    float4 wa = __ldg(&reinterpret_cast<const float4*>(Wa)[lane]);
    float4 wb = __ldg(&reinterpret_cast<const float4*>(Wa + 128)[lane]);
    float dA = x.x * wa.x + x.y * wa.y + x.z * wa.z + x.w * wa.w;
    float dB = x.x * wb.x + x.y * wb.y + x.z * wb.z + x.w * wb.w;
#pragma unroll
    for (int off = 16; off > 0; off >>= 1) {
        dA += __shfl_down_sync(0xffffffffu, dA, off);
        dB += __shfl_down_sync(0xffffffffu, dB, off);
    }
    if (lane == 0) { sA[n] = dA; sB[n] = dB; }
}

// ---------------- column mean of X[M,128] into out[128] (pre-zeroed) ----------------
__global__ void colmean_kernel(const float* __restrict__ X, float* __restrict__ out, int M)
{
    __shared__ float s[256];
    int c = threadIdx.x & 127;
    int half = threadIdx.x >> 7;
    float acc = 0.f;
    for (int r = blockIdx.x * 2 + half; r < M; r += gridDim.x * 2)
        acc += X[(size_t)r * 128 + c];
    s[threadIdx.x] = acc;
    __syncthreads();
    if (half == 0) atomicAdd(&out[c], (s[c] + s[c + 128]) * (1.0f / (float)M));
}

// ---------------- fold Q-mean block of W_mt into bias ----------------
__global__ void bmt_eff_kernel(const float* __restrict__ qmean, const float* __restrict__ W_mt,
                               const float* __restrict__ b_mt, float* __restrict__ beff)
{
    int j = threadIdx.x;            // 0..127
    float acc = __ldg(&b_mt[j]);
    for (int k = 0; k < 128; k++)
        acc += qmean[k] * __ldg(&W_mt[(size_t)(256 + k) * 128 + j]);
    beff[j] = acc;
}

// ---------------- finalize: + mask*(V2+b) term, or select merged if only_run_inter ----------------
__global__ void finalize_kernel(const int* __restrict__ flag, const float* __restrict__ merged,
                                const float* __restrict__ V2b, const float* __restrict__ sums,
                                float* __restrict__ out, int N)
{
    int i = blockIdx.x * blockDim.x + threadIdx.x;
    if (i >= N * 128) return;
    if (*flag) out[i] = merged[i];
    else if (__ldg(&sums[i >> 7]) > 0.f) out[i] += V2b[i];
}

// ============================================================================
extern "C" void kernel_launch(void* const* d_in, const int* in_sizes, int n_in,
                              void* d_out, int out_size)
{
    const float* Xq        = (const float*)d_in[0];
    const int*   eiq       = (const int*)  d_in[1];
    const float* Xt        = (const float*)d_in[2];
    const int*   eit       = (const int*)  d_in[3];
    const int*   cr_src    = (const int*)  d_in[6];
    const int*   cr_dst    = (const int*)  d_in[7];
    const int*   flag      = (const int*)  d_in[9];
    const float* W_ac_q    = (const float*)d_in[10]; const float* b_ac_q = (const float*)d_in[11];
    const float* W_ac_t    = (const float*)d_in[12]; const float* b_ac_t = (const float*)d_in[13];
    const float* W_vc_q    = (const float*)d_in[14]; const float* b_vc_q = (const float*)d_in[15];
    const float* W_vc_t    = (const float*)d_in[16]; const float* b_vc_t = (const float*)d_in[17];
    const float* W_mq      = (const float*)d_in[18]; const float* b_mq   = (const float*)d_in[19];
    const float* W_mt      = (const float*)d_in[20]; const float* b_mt   = (const float*)d_in[21];
    const float* W_aq      = (const float*)d_in[22]; const float* b_aq   = (const float*)d_in[23];
    const float* W_vq      = (const float*)d_in[24]; const float* b_vq   = (const float*)d_in[25];
    const float* W_at      = (const float*)d_in[26]; const float* b_at   = (const float*)d_in[27];
    const float* W_vt      = (const float*)d_in[28]; const float* b_vt   = (const float*)d_in[29];

    const int nq = in_sizes[0] / DD;
    const int nt = in_sizes[2] / DD;
    const int ec = in_sizes[6];
    const int eq = in_sizes[1] / 2;
    const int et = in_sizes[3] / 2;

    float *Xq_ac, *Xt_ac, *Xq_vc, *Xt_vc, *Xq2t, *Xt2q, *Xq_m, *Xt_m;
    float *V1q, *V2q, *V1t, *V2t, *logits;
    float *maxq, *sumq, *maxt, *sumt, *maxd_t, *sumd_t, *maxd_q, *sumd_q;
    float *sAt, *sBt, *sAq, *sBq, *qmean, *bmt;
    cudaGetSymbolAddress((void**)&Xq_ac, g_Xq_ac);
    cudaGetSymbolAddress((void**)&Xt_ac, g_Xt_ac);
    cudaGetSymbolAddress((void**)&Xq_vc, g_Xq_vc);
    cudaGetSymbolAddress((void**)&Xt_vc, g_Xt_vc);
    cudaGetSymbolAddress((void**)&Xq2t,  g_Xq2t);
    cudaGetSymbolAddress((void**)&Xt2q,  g_Xt2q);
    cudaGetSymbolAddress((void**)&Xq_m,  g_Xq_m);
    cudaGetSymbolAddress((void**)&Xt_m,  g_Xt_m);
    cudaGetSymbolAddress((void**)&V1q,   g_V1q);
    cudaGetSymbolAddress((void**)&V2q,   g_V2q);
    cudaGetSymbolAddress((void**)&V1t,   g_V1t);
    cudaGetSymbolAddress((void**)&V2t,   g_V2t);
    cudaGetSymbolAddress((void**)&logits,g_logits);
    cudaGetSymbolAddress((void**)&maxq,  g_maxq);
    cudaGetSymbolAddress((void**)&sumq,  g_sumq);
    cudaGetSymbolAddress((void**)&maxt,  g_maxt);
    cudaGetSymbolAddress((void**)&sumt,  g_sumt);
    cudaGetSymbolAddress((void**)&maxd_t,g_maxd_t);
    cudaGetSymbolAddress((void**)&sumd_t,g_sumd_t);
    cudaGetSymbolAddress((void**)&maxd_q,g_maxd_q);
    cudaGetSymbolAddress((void**)&sumd_q,g_sumd_q);
    cudaGetSymbolAddress((void**)&sAt,   g_sAt);
    cudaGetSymbolAddress((void**)&sBt,   g_sBt);
    cudaGetSymbolAddress((void**)&sAq,   g_sAq);
    cudaGetSymbolAddress((void**)&sBq,   g_sBq);
    cudaGetSymbolAddress((void**)&qmean, g_qmean);
    cudaGetSymbolAddress((void**)&bmt,   g_bmt);

    float* out_q = (float*)d_out;
    float* out_t = (float*)d_out + (size_t)nq * DD;

    const int T = 256;
    const float NEG_INF = -INFINITY;
#define FILL(p, v, n) fillf_kernel<<<((n) + T - 1) / T, T>>>((p), (v), (n))

    // 1) elu projections
    gemm2_kernel<<<(nq + 31) / 32, 256>>>(Xq, Xq, DD, 0, W_ac_q, b_ac_q, Xq_ac, 1, nq);
    gemm2_kernel<<<(nt + 31) / 32, 256>>>(Xt, Xt, DD, 0, W_ac_t, b_ac_t, Xt_ac, 1, nt);
    gemm2_kernel<<<(nq + 31) / 32, 256>>>(Xq, Xq, DD, 0, W_vc_q, b_vc_q, Xq_vc, 1, nq);
    gemm2_kernel<<<(nt + 31) / 32, 256>>>(Xt, Xt, DD, 0, W_vc_t, b_vc_t, Xt_vc, 1, nt);

    // 2) init cross-softmax state
    FILL(maxq, NEG_INF, nq); FILL(maxt, NEG_INF, nt);
    FILL(sumq, 0.f, nq);     FILL(sumt, 0.f, nt);
    FILL(Xq2t, 0.f, nt * DD);
    FILL(qmean, 0.f, DD);

    // 3) cross attention
    cross_dot_max<<<(ec + 7) / 8, 256>>>(cr_src, cr_dst, Xq_ac, Xt_ac, logits, maxq, maxt, ec);
    cross_expsum<<<(ec + T - 1) / T, T>>>(cr_src, cr_dst, logits, maxq, maxt, sumq, sumt, ec);
    edge_scatter<<<(ec + 7) / 8, 256>>>(cr_src, cr_dst, logits, maxt, sumt, Xq_vc, Xq2t, ec);
    mask_copy<<<(nq * DD + T - 1) / T, T>>>(Xt_vc, sumq, Xt2q, nq);

    // 4) Q-mean folded bias for W_mt
    colmean_kernel<<<64, 256>>>(Xq, qmean, nq);
    bmt_eff_kernel<<<1, 128>>>(qmean, W_mt, b_mt, bmt);

    // 5) merge GEMMs
    gemm2_kernel<<<(nq + 31) / 32, 256>>>(Xq, Xt2q, DD, DD, W_mq, b_mq, Xq_m, 0, nq);
    gemm2_kernel<<<(nt + 31) / 32, 256>>>(Xt, Xq2t, DD, DD, W_mt, bmt, Xt_m, 0, nt);

    // 6) intra precompute (per-node scalars + value projections)
    node_scalar<<<(nt * 32 + T - 1) / T, T>>>(Xt_m, W_at, sAt, sBt, nt);
    node_scalar<<<(nq * 32 + T - 1) / T, T>>>(Xq_m, W_aq, sAq, sBq, nq);
    gemm2_kernel<<<(nt + 31) / 32, 256>>>(Xt_m, Xt_m, DD, 0, W_vt,            nullptr, V1t, 0, nt);
    gemm2_kernel<<<(nt + 31) / 32, 256>>>(Xt_m, Xt_m, DD, 0, W_vt + 128 * 128, b_vt,   V2t, 0, nt);
    gemm2_kernel<<<(nq + 31) / 32, 256>>>(Xq_m, Xq_m, DD, 0, W_vq,            nullptr, V1q, 0, nq);
    gemm2_kernel<<<(nq + 31) / 32, 256>>>(Xq_m, Xq_m, DD, 0, W_vq + 128 * 128, b_vq,   V2q, 0, nq);

    // 7) intra t-graph
    FILL(maxd_t, NEG_INF, nt); FILL(sumd_t, 0.f, nt);
    FILL(out_t, 0.f, nt * DD);
    intra_logit_max<<<(et + T - 1) / T, T>>>(eit, eit + et, sAt, sBt, b_at, logits, maxd_t, et);
    expsum1<<<(et + T - 1) / T, T>>>(eit + et, logits, maxd_t, sumd_t, et);
    edge_scatter<<<(et + 7) / 8, 256>>>(eit, eit + et, logits, maxd_t, sumd_t, V1t, out_t, et);

    // 8) intra q-graph
    FILL(maxd_q, NEG_INF, nq); FILL(sumd_q, 0.f, nq);
    FILL(out_q, 0.f, nq * DD);
    intra_logit_max<<<(eq + T - 1) / T, T>>>(eiq, eiq + eq, sAq, sBq, b_aq, logits, maxd_q, eq);
    expsum1<<<(eq + T - 1) / T, T>>>(eiq + eq, logits, maxd_q, sumd_q, eq);
    edge_scatter<<<(eq + 7) / 8, 256>>>(eiq, eiq + eq, logits, maxd_q, sumd_q, V1q, out_q, eq);

    // 9) finalize (+V2 mask term, or merged if only_run_inter)
    finalize_kernel<<<(nq * DD + T - 1) / T, T>>>(flag, Xq_m, V2q, sumd_q, out_q, nq);
    finalize_kernel<<<(nt * DD + T - 1) / T, T>>>(flag, Xt_m, V2t, sumd_t, out_t, nt);
#undef FILL
}

// round 8
// speedup vs baseline: 1.0388x; 1.0388x over previous
#include <cuda_runtime.h>
#include <math.h>

#define DD 128
#define NQ_MAX 8192
#define NT_MAX 8192
#define E_MAX  262144

// ---------------- scratch (static device allocations; no cudaMalloc) ----------------
__device__ float g_Xq_ac[NQ_MAX*DD];
__device__ float g_Xt_ac[NT_MAX*DD];
__device__ float g_Xq_vc[NQ_MAX*DD];
__device__ float g_Xt_vc[NT_MAX*DD];
__device__ float g_Xq2t [NT_MAX*DD];
__device__ float g_Xt2q [NQ_MAX*DD];
__device__ float g_Xq_m [NQ_MAX*DD];
__device__ float g_Xt_m [NT_MAX*DD];
__device__ float g_V1q  [NQ_MAX*DD];
__device__ float g_V2q  [NQ_MAX*DD];
__device__ float g_V1t  [NT_MAX*DD];
__device__ float g_V2t  [NT_MAX*DD];
__device__ float g_logits[E_MAX];
__device__ float g_maxq[NQ_MAX];
__device__ float g_sumq[NQ_MAX];
__device__ float g_maxt[NT_MAX];
__device__ float g_sumt[NT_MAX];
__device__ float g_maxd_t[NT_MAX];
__device__ float g_sumd_t[NT_MAX];
__device__ float g_maxd_q[NQ_MAX];
__device__ float g_sumd_q[NQ_MAX];
__device__ float g_sAt[NT_MAX];
__device__ float g_sBt[NT_MAX];
__device__ float g_sAq[NQ_MAX];
__device__ float g_sBq[NQ_MAX];
__device__ float g_qmean[DD];
__device__ float g_bmt[DD];

// ---------------- helpers ----------------
__device__ __forceinline__ void atomicMaxF(float* addr, float v) {
    // monotone bit trick: valid for all non-NaN floats
    if (v >= 0.0f) atomicMax((int*)addr, __float_as_int(v));
    else           atomicMin((unsigned int*)addr, (unsigned int)__float_as_int(v));
}

__global__ void fillf_kernel(float* __restrict__ p, float v, int n) {
    int i = blockIdx.x * blockDim.x + threadIdx.x;
    if (i < n) p[i] = v;
}

// ---------------- GEMM: C[M,128] = concat(A1[M,k1], A2[M,k2]) @ B[K,128] + bias, opt ELU ----------------
__global__ void gemm2_kernel(const float* __restrict__ A1, const float* __restrict__ A2,
                             int k1, int k2,
                             const float* __restrict__ B, const float* __restrict__ bias,
                             float* __restrict__ C, int doElu, int M)
{
    const int K = k1 + k2;
    __shared__ __align__(16) float As[32][33];
    __shared__ __align__(16) float Bs[32][128];
    const int tid = threadIdx.x;
    const int tx = tid & 15;         // col group
    const int ty = tid >> 4;         // row group (2 rows each)
    const int m0 = blockIdx.x * 32;
    if (m0 >= M) return;

    float acc0[8], acc1[8];
#pragma unroll
    for (int j = 0; j < 8; j++) { acc0[j] = 0.f; acc1[j] = 0.f; }

    for (int kk = 0; kk < K; kk += 32) {
#pragma unroll
        for (int i = tid; i < 1024; i += 256) {
            int m = i >> 5, k = i & 31;
            int col = kk + k;
            float v = (col < k1) ? __ldg(&A1[(size_t)(m0 + m) * k1 + col])
                                 : __ldg(&A2[(size_t)(m0 + m) * k2 + (col - k1)]);
            As[k][m] = v;
        }
#pragma unroll
        for (int i = tid; i < 4096; i += 256) {
            int k = i >> 7, n = i & 127;
            Bs[k][n] = __ldg(&B[(size_t)(kk + k) * 128 + n]);
        }
        __syncthreads();
#pragma unroll
        for (int k = 0; k < 32; k++) {
            float a0 = As[k][ty * 2 + 0];
            float a1 = As[k][ty * 2 + 1];
            const float4* bp = reinterpret_cast<const float4*>(&Bs[k][tx * 8]);
            float4 b0 = bp[0], b1 = bp[1];
            acc0[0] += a0 * b0.x; acc0[1] += a0 * b0.y; acc0[2] += a0 * b0.z; acc0[3] += a0 * b0.w;
            acc0[4] += a0 * b1.x; acc0[5] += a0 * b1.y; acc0[6] += a0 * b1.z; acc0[7] += a0 * b1.w;
            acc1[0] += a1 * b0.x; acc1[1] += a1 * b0.y; acc1[2] += a1 * b0.z; acc1[3] += a1 * b0.w;
            acc1[4] += a1 * b1.x; acc1[5] += a1 * b1.y; acc1[6] += a1 * b1.z; acc1[7] += a1 * b1.w;
        }
        __syncthreads();
    }

    const int r0 = m0 + ty * 2;
    const int c0 = tx * 8;
    float bb[8];
#pragma unroll
    for (int j = 0; j < 8; j++) bb[j] = bias ? __ldg(&bias[c0 + j]) : 0.f;
#pragma unroll
    for (int j = 0; j < 8; j++) {
        float v0 = acc0[j] + bb[j];
        float v1 = acc1[j] + bb[j];
        if (doElu) {
            v0 = v0 > 0.f ? v0 : expm1f(v0);
            v1 = v1 > 0.f ? v1 : expm1f(v1);
        }
        acc0[j] = v0; acc1[j] = v1;
    }
    float4* o0 = reinterpret_cast<float4*>(&C[(size_t)r0 * 128 + c0]);
    float4* o1 = reinterpret_cast<float4*>(&C[(size_t)(r0 + 1) * 128 + c0]);
    o0[0] = make_float4(acc0[0], acc0[1], acc0[2], acc0[3]);
    o0[1] = make_float4(acc0[4], acc0[5], acc0[6], acc0[7]);
    o1[0] = make_float4(acc1[0], acc1[1], acc1[2], acc1[3]);
    o1[1] = make_float4(acc1[4], acc1[5], acc1[6], acc1[7]);
}

// ---------------- cross pass1: per-edge 128-d dot + segment max (both seg maps) ----------------
__global__ void cross_dot_max(const int* __restrict__ src, const int* __restrict__ dst,
                              const float* __restrict__ Xa, const float* __restrict__ Xb,
                              float* __restrict__ logits,
                              float* __restrict__ maxs, float* __restrict__ maxd, int E)
{
    int e = (blockIdx.x * blockDim.x + threadIdx.x) >> 5;
    int lane = threadIdx.x & 31;
    if (e >= E) return;
    int s = __ldg(&src[e]), t = __ldg(&dst[e]);
    float4 a = __ldg(&reinterpret_cast<const float4*>(Xa + (size_t)s * 128)[lane]);
    float4 b = __ldg(&reinterpret_cast<const float4*>(Xb + (size_t)t * 128)[lane]);
    float d = a.x * b.x + a.y * b.y + a.z * b.z + a.w * b.w;
#pragma unroll
    for (int off = 16; off > 0; off >>= 1) d += __shfl_down_sync(0xffffffffu, d, off);
    if (lane == 0) {
        logits[e] = d;
        atomicMaxF(&maxs[s], d);
        atomicMaxF(&maxd[t], d);
    }
}

// ---------------- cross pass2: exp-sums for both segmentations ----------------
__global__ void cross_expsum(const int* __restrict__ src, const int* __restrict__ dst,
                             const float* __restrict__ logits,
                             const float* __restrict__ maxs, const float* __restrict__ maxd,
                             float* __restrict__ sums, float* __restrict__ sumd, int E)
{
    int e = blockIdx.x * blockDim.x + threadIdx.x;
    if (e >= E) return;
    float l = logits[e];
    int s = __ldg(&src[e]), t = __ldg(&dst[e]);
    atomicAdd(&sums[s], expf(l - __ldg(&maxs[s])));
    atomicAdd(&sumd[t], expf(l - __ldg(&maxd[t])));
}

// ---------------- intra pass1: logit from per-node scalars + segment max (dst only) ----------------
__global__ void intra_logit_max(const int* __restrict__ src, const int* __restrict__ dst,
                                const float* __restrict__ sA, const float* __restrict__ sB,
                                const float* __restrict__ ba,
                                float* __restrict__ logits, float* __restrict__ maxd, int E)
{
    int e = blockIdx.x * blockDim.x + threadIdx.x;
    if (e >= E) return;
    int t = __ldg(&dst[e]);
    float l = __ldg(&sA[__ldg(&src[e])]) + __ldg(&sB[t]) + __ldg(&ba[0]);
    logits[e] = l;
    atomicMaxF(&maxd[t], l);
}

// ---------------- intra pass2: exp-sum (dst only) ----------------
__global__ void expsum1(const int* __restrict__ dst, const float* __restrict__ logits,
                        const float* __restrict__ maxd, float* __restrict__ sumd, int E)
{
    int e = blockIdx.x * blockDim.x + threadIdx.x;
    if (e >= E) return;
    int t = __ldg(&dst[e]);
    atomicAdd(&sumd[t], expf(logits[e] - __ldg(&maxd[t])));
}

// ---------------- pass3: out[dst] += softmax_weight * V[src] (warp/edge, float atomics) ----------------
__global__ void edge_scatter(const int* __restrict__ src, const int* __restrict__ dst,
                             const float* __restrict__ logits,
                             const float* __restrict__ maxd, const float* __restrict__ sumd,
                             const float* __restrict__ V, float* __restrict__ out, int E)
{
    int e = (blockIdx.x * blockDim.x + threadIdx.x) >> 5;
    int lane = threadIdx.x & 31;
    if (e >= E) return;
    int s = __ldg(&src[e]), t = __ldg(&dst[e]);
    float a = expf(logits[e] - __ldg(&maxd[t])) / __ldg(&sumd[t]);
    float4 v = __ldg(&reinterpret_cast<const float4*>(V + (size_t)s * 128)[lane]);
    float* o = out + (size_t)t * 128 + lane * 4;
    atomicAdd(o + 0, a * v.x);
    atomicAdd(o + 1, a * v.y);
    atomicAdd(o + 2, a * v.z);
    atomicAdd(o + 3, a * v.w);
}

// ---------------- Xt2q shortcut: masked copy ----------------
__global__ void mask_copy(const float* __restrict__ X, const float* __restrict__ sums,
                          float* __restrict__ out, int N)
{
    int i = blockIdx.x * blockDim.x + threadIdx.x;
    if (i >= N * 128) return;
    out[i] = (__ldg(&sums[i >> 7]) > 0.f) ? X[i] : 0.f;
}

// ---------------- per-node scalar dots sA = X.W[0:128], sB = X.W[128:256] ----------------
__global__ void node_scalar(const float* __restrict__ X, const float* __restrict__ Wa,
                            float* __restrict__ sA, float* __restrict__ sB, int N)
{
    int n = (blockIdx.x * blockDim.x + threadIdx.x) >> 5;
    int lane = threadIdx.x & 31;
    if (n >= N) return;
    float4 x  = __ldg(&reinterpret_cast<const float4*>(X + (size_t)n * 128)[lane]);
    float4 wa = __ldg(&reinterpret_cast<const float4*>(Wa)[lane]);
    float4 wb = __ldg(&reinterpret_cast<const float4*>(Wa + 128)[lane]);
    float dA = x.x * wa.x + x.y * wa.y + x.z * wa.z + x.w * wa.w;
    float dB = x.x * wb.x + x.y * wb.y + x.z * wb.z + x.w * wb.w;
#pragma unroll
    for (int off = 16; off > 0; off >>= 1) {
        dA += __shfl_down_sync(0xffffffffu, dA, off);
        dB += __shfl_down_sync(0xffffffffu, dB, off);
    }
    if (lane == 0) { sA[n] = dA; sB[n] = dB; }
}

// ---------------- column mean of X[M,128] into out[128] (pre-zeroed) ----------------
__global__ void colmean_kernel(const float* __restrict__ X, float* __restrict__ out, int M)
{
    __shared__ float s[256];
    int c = threadIdx.x & 127;
    int half = threadIdx.x >> 7;
    float acc = 0.f;
    for (int r = blockIdx.x * 2 + half; r < M; r += gridDim.x * 2)
        acc += X[(size_t)r * 128 + c];
    s[threadIdx.x] = acc;
    __syncthreads();
    if (half == 0) atomicAdd(&out[c], (s[c] + s[c + 128]) * (1.0f / (float)M));
}

// ---------------- fold Q-mean block of W_mt into bias ----------------
__global__ void bmt_eff_kernel(const float* __restrict__ qmean, const float* __restrict__ W_mt,
                               const float* __restrict__ b_mt, float* __restrict__ beff)
{
    int j = threadIdx.x;            // 0..127
    float acc = __ldg(&b_mt[j]);
    for (int k = 0; k < 128; k++)
        acc += qmean[k] * __ldg(&W_mt[(size_t)(256 + k) * 128 + j]);
    beff[j] = acc;
}

// ---------------- finalize: + mask*(V2+b) term, or select merged if only_run_inter ----------------
__global__ void finalize_kernel(const int* __restrict__ flag, const float* __restrict__ merged,
                                const float* __restrict__ V2b, const float* __restrict__ sums,
                                float* __restrict__ out, int N)
{
    int i = blockIdx.x * blockDim.x + threadIdx.x;
    if (i >= N * 128) return;
    if (*flag) out[i] = merged[i];
    else if (__ldg(&sums[i >> 7]) > 0.f) out[i] += V2b[i];
}

// ============================================================================
extern "C" void kernel_launch(void* const* d_in, const int* in_sizes, int n_in,
                              void* d_out, int out_size)
{
    const float* Xq        = (const float*)d_in[0];
    const int*   eiq       = (const int*)  d_in[1];
    const float* Xt        = (const float*)d_in[2];
    const int*   eit       = (const int*)  d_in[3];
    const int*   cr_src    = (const int*)  d_in[6];
    const int*   cr_dst    = (const int*)  d_in[7];
    const int*   flag      = (const int*)  d_in[9];
    const float* W_ac_q    = (const float*)d_in[10]; const float* b_ac_q = (const float*)d_in[11];
    const float* W_ac_t    = (const float*)d_in[12]; const float* b_ac_t = (const float*)d_in[13];
    const float* W_vc_q    = (const float*)d_in[14]; const float* b_vc_q = (const float*)d_in[15];
    const float* W_vc_t    = (const float*)d_in[16]; const float* b_vc_t = (const float*)d_in[17];
    const float* W_mq      = (const float*)d_in[18]; const float* b_mq   = (const float*)d_in[19];
    const float* W_mt      = (const float*)d_in[20]; const float* b_mt   = (const float*)d_in[21];
    const float* W_aq      = (const float*)d_in[22]; const float* b_aq   = (const float*)d_in[23];
    const float* W_vq      = (const float*)d_in[24]; const float* b_vq   = (const float*)d_in[25];
    const float* W_at      = (const float*)d_in[26]; const float* b_at   = (const float*)d_in[27];
    const float* W_vt      = (const float*)d_in[28]; const float* b_vt   = (const float*)d_in[29];

    const int nq = in_sizes[0] / DD;
    const int nt = in_sizes[2] / DD;
    const int ec = in_sizes[6];
    const int eq = in_sizes[1] / 2;
    const int et = in_sizes[3] / 2;

    float *Xq_ac, *Xt_ac, *Xq_vc, *Xt_vc, *Xq2t, *Xt2q, *Xq_m, *Xt_m;
    float *V1q, *V2q, *V1t, *V2t, *logits;
    float *maxq, *sumq, *maxt, *sumt, *maxd_t, *sumd_t, *maxd_q, *sumd_q;
    float *sAt, *sBt, *sAq, *sBq, *qmean, *bmt;
    cudaGetSymbolAddress((void**)&Xq_ac, g_Xq_ac);
    cudaGetSymbolAddress((void**)&Xt_ac, g_Xt_ac);
    cudaGetSymbolAddress((void**)&Xq_vc, g_Xq_vc);
    cudaGetSymbolAddress((void**)&Xt_vc, g_Xt_vc);
    cudaGetSymbolAddress((void**)&Xq2t,  g_Xq2t);
    cudaGetSymbolAddress((void**)&Xt2q,  g_Xt2q);
    cudaGetSymbolAddress((void**)&Xq_m,  g_Xq_m);
    cudaGetSymbolAddress((void**)&Xt_m,  g_Xt_m);
    cudaGetSymbolAddress((void**)&V1q,   g_V1q);
    cudaGetSymbolAddress((void**)&V2q,   g_V2q);
    cudaGetSymbolAddress((void**)&V1t,   g_V1t);
    cudaGetSymbolAddress((void**)&V2t,   g_V2t);
    cudaGetSymbolAddress((void**)&logits,g_logits);
    cudaGetSymbolAddress((void**)&maxq,  g_maxq);
    cudaGetSymbolAddress((void**)&sumq,  g_sumq);
    cudaGetSymbolAddress((void**)&maxt,  g_maxt);
    cudaGetSymbolAddress((void**)&sumt,  g_sumt);
    cudaGetSymbolAddress((void**)&maxd_t,g_maxd_t);
    cudaGetSymbolAddress((void**)&sumd_t,g_sumd_t);
    cudaGetSymbolAddress((void**)&maxd_q,g_maxd_q);
    cudaGetSymbolAddress((void**)&sumd_q,g_sumd_q);
    cudaGetSymbolAddress((void**)&sAt,   g_sAt);
    cudaGetSymbolAddress((void**)&sBt,   g_sBt);
    cudaGetSymbolAddress((void**)&sAq,   g_sAq);
    cudaGetSymbolAddress((void**)&sBq,   g_sBq);
    cudaGetSymbolAddress((void**)&qmean, g_qmean);
    cudaGetSymbolAddress((void**)&bmt,   g_bmt);

    float* out_q = (float*)d_out;
    float* out_t = (float*)d_out + (size_t)nq * DD;

    const int T = 256;
    const float NEG_INF = -INFINITY;
#define FILL(p, v, n) fillf_kernel<<<((n) + T - 1) / T, T>>>((p), (v), (n))

    // 1) elu projections
    gemm2_kernel<<<(nq + 31) / 32, 256>>>(Xq, Xq, DD, 0, W_ac_q, b_ac_q, Xq_ac, 1, nq);
    gemm2_kernel<<<(nt + 31) / 32, 256>>>(Xt, Xt, DD, 0, W_ac_t, b_ac_t, Xt_ac, 1, nt);
    gemm2_kernel<<<(nq + 31) / 32, 256>>>(Xq, Xq, DD, 0, W_vc_q, b_vc_q, Xq_vc, 1, nq);
    gemm2_kernel<<<(nt + 31) / 32, 256>>>(Xt, Xt, DD, 0, W_vc_t, b_vc_t, Xt_vc, 1, nt);

    // 2) init cross-softmax state
    FILL(maxq, NEG_INF, nq); FILL(maxt, NEG_INF, nt);
    FILL(sumq, 0.f, nq);     FILL(sumt, 0.f, nt);
    FILL(Xq2t, 0.f, nt * DD);
    FILL(qmean, 0.f, DD);

    // 3) cross attention
    cross_dot_max<<<(ec + 7) / 8, 256>>>(cr_src, cr_dst, Xq_ac, Xt_ac, logits, maxq, maxt, ec);
    cross_expsum<<<(ec + T - 1) / T, T>>>(cr_src, cr_dst, logits, maxq, maxt, sumq, sumt, ec);
    edge_scatter<<<(ec + 7) / 8, 256>>>(cr_src, cr_dst, logits, maxt, sumt, Xq_vc, Xq2t, ec);
    mask_copy<<<(nq * DD + T - 1) / T, T>>>(Xt_vc, sumq, Xt2q, nq);

    // 4) Q-mean folded bias for W_mt
    colmean_kernel<<<64, 256>>>(Xq, qmean, nq);
    bmt_eff_kernel<<<1, 128>>>(qmean, W_mt, b_mt, bmt);

    // 5) merge GEMMs
    gemm2_kernel<<<(nq + 31) / 32, 256>>>(Xq, Xt2q, DD, DD, W_mq, b_mq, Xq_m, 0, nq);
    gemm2_kernel<<<(nt + 31) / 32, 256>>>(Xt, Xq2t, DD, DD, W_mt, bmt, Xt_m, 0, nt);

    // 6) intra precompute (per-node scalars + value projections)
    node_scalar<<<(nt * 32 + T - 1) / T, T>>>(Xt_m, W_at, sAt, sBt, nt);
    node_scalar<<<(nq * 32 + T - 1) / T, T>>>(Xq_m, W_aq, sAq, sBq, nq);
    gemm2_kernel<<<(nt + 31) / 32, 256>>>(Xt_m, Xt_m, DD, 0, W_vt,            nullptr, V1t, 0, nt);
    gemm2_kernel<<<(nt + 31) / 32, 256>>>(Xt_m, Xt_m, DD, 0, W_vt + 128 * 128, b_vt,   V2t, 0, nt);
    gemm2_kernel<<<(nq + 31) / 32, 256>>>(Xq_m, Xq_m, DD, 0, W_vq,            nullptr, V1q, 0, nq);
    gemm2_kernel<<<(nq + 31) / 32, 256>>>(Xq_m, Xq_m, DD, 0, W_vq + 128 * 128, b_vq,   V2q, 0, nq);

    // 7) intra t-graph
    FILL(maxd_t, NEG_INF, nt); FILL(sumd_t, 0.f, nt);
    FILL(out_t, 0.f, nt * DD);
    intra_logit_max<<<(et + T - 1) / T, T>>>(eit, eit + et, sAt, sBt, b_at, logits, maxd_t, et);
    expsum1<<<(et + T - 1) / T, T>>>(eit + et, logits, maxd_t, sumd_t, et);
    edge_scatter<<<(et + 7) / 8, 256>>>(eit, eit + et, logits, maxd_t, sumd_t, V1t, out_t, et);

    // 8) intra q-graph
    FILL(maxd_q, NEG_INF, nq); FILL(sumd_q, 0.f, nq);
    FILL(out_q, 0.f, nq * DD);
    intra_logit_max<<<(eq + T - 1) / T, T>>>(eiq, eiq + eq, sAq, sBq, b_aq, logits, maxd_q, eq);
    expsum1<<<(eq + T - 1) / T, T>>>(eiq + eq, logits, maxd_q, sumd_q, eq);
    edge_scatter<<<(eq + 7) / 8, 256>>>(eiq, eiq + eq, logits, maxd_q, sumd_q, V1q, out_q, eq);

    // 9) finalize (+V2 mask term, or merged if only_run_inter)
    finalize_kernel<<<(nq * DD + T - 1) / T, T>>>(flag, Xq_m, V2q, sumd_q, out_q, nq);
    finalize_kernel<<<(nt * DD + T - 1) / T, T>>>(flag, Xt_m, V2t, sumd_t, out_t, nt);
#undef FILL
}

// round 11
// speedup vs baseline: 1.2709x; 1.2235x over previous
#include <cuda_runtime.h>
#include <math.h>

#define DD 128
#define NQ_MAX 8192
#define NT_MAX 8192
#define E_MAX  262144
#define SCAN_T 1024

// ---------------- scratch (static device allocations; no cudaMalloc) ----------------
__device__ float g_Xq_ac[NQ_MAX*DD];
__device__ float g_Xt_ac[NT_MAX*DD];
__device__ float g_Xq_vc[NQ_MAX*DD];
__device__ float g_Xt_vc[NT_MAX*DD];
__device__ float g_Xq2t [NT_MAX*DD];
__device__ float g_Xt2q [NQ_MAX*DD];
__device__ float g_Xq_m [NQ_MAX*DD];
__device__ float g_Xt_m [NT_MAX*DD];
__device__ float g_V1q  [NQ_MAX*DD];
__device__ float g_V2q  [NQ_MAX*DD];
__device__ float g_V1t  [NT_MAX*DD];
__device__ float g_V2t  [NT_MAX*DD];
__device__ float g_logits[E_MAX];
__device__ float g_sAt[NT_MAX];
__device__ float g_sAq[NQ_MAX];
__device__ float g_qmean[DD];
__device__ float g_bmt[DD];
// CSR scratch (reused sequentially for cross / t-graph / q-graph)
__device__ int   g_count [NQ_MAX + 1];
__device__ int   g_start [NQ_MAX + 1];
__device__ int   g_cursor[NQ_MAX + 1];
__device__ int   g_eid   [E_MAX];
__device__ int   g_degsrc[NQ_MAX];

// ---------------- small utility kernels ----------------
__global__ void fillf_kernel(float* __restrict__ p, float v, int n) {
    int i = blockIdx.x * blockDim.x + threadIdx.x;
    if (i < n) p[i] = v;
}
__global__ void filli_kernel(int* __restrict__ p, int v, int n) {
    int i = blockIdx.x * blockDim.x + threadIdx.x;
    if (i < n) p[i] = v;
}

// ---------------- CSR build ----------------
__global__ void count_kernel(const int* __restrict__ idx, int* __restrict__ count, int E) {
    int e = blockIdx.x * blockDim.x + threadIdx.x;
    if (e < E) atomicAdd(&count[__ldg(&idx[e])], 1);
}

// single block, SCAN_T threads, 8 elems/thread; N <= 8192
__global__ void scan_kernel(const int* __restrict__ count, int* __restrict__ start,
                            int* __restrict__ cursor, int N)
{
    __shared__ int s[SCAN_T];
    int tid = threadIdx.x;
    int base = tid * 8;
    int local[8];
    int acc = 0;
#pragma unroll
    for (int j = 0; j < 8; j++) {
        int v = (base + j < N) ? count[base + j] : 0;
        local[j] = acc;
        acc += v;
    }
    s[tid] = acc;
    __syncthreads();
    for (int off = 1; off < SCAN_T; off <<= 1) {
        int v = 0;
        if (tid >= off) v = s[tid - off];
        __syncthreads();
        if (tid >= off) s[tid] += v;
        __syncthreads();
    }
    int offset = (tid > 0) ? s[tid - 1] : 0;
#pragma unroll
    for (int j = 0; j < 8; j++) {
        int idx = base + j;
        if (idx < N) {
            int v = offset + local[j];
            start[idx]  = v;
            cursor[idx] = v;
        }
    }
    if (tid == SCAN_T - 1) start[N] = s[SCAN_T - 1];
}

__global__ void fill_kernel(const int* __restrict__ idx, int* __restrict__ cursor,
                            int* __restrict__ eid, int E)
{
    int e = blockIdx.x * blockDim.x + threadIdx.x;
    if (e >= E) return;
    int p = atomicAdd(&cursor[__ldg(&idx[e])], 1);
    eid[p] = e;
}

// ---------------- GEMM: C[M,128] = concat(A1[M,k1], A2[M,k2]) @ B[K,128] + bias, opt ELU ----------------
__global__ void gemm2_kernel(const float* __restrict__ A1, const float* __restrict__ A2,
                             int k1, int k2,
                             const float* __restrict__ B, const float* __restrict__ bias,
                             float* __restrict__ C, int doElu, int M)
{
    const int K = k1 + k2;
    __shared__ __align__(16) float As[32][33];
    __shared__ __align__(16) float Bs[32][128];
    const int tid = threadIdx.x;
    const int tx = tid & 15;         // col group
    const int ty = tid >> 4;         // row group (2 rows each)
    const int m0 = blockIdx.x * 32;
    if (m0 >= M) return;

    float acc0[8], acc1[8];
#pragma unroll
    for (int j = 0; j < 8; j++) { acc0[j] = 0.f; acc1[j] = 0.f; }

    for (int kk = 0; kk < K; kk += 32) {
#pragma unroll
        for (int i = tid; i < 1024; i += 256) {
            int m = i >> 5, k = i & 31;
            int col = kk + k;
            float v = (col < k1) ? __ldg(&A1[(size_t)(m0 + m) * k1 + col])
                                 : __ldg(&A2[(size_t)(m0 + m) * k2 + (col - k1)]);
            As[k][m] = v;
        }
#pragma unroll
        for (int i = tid; i < 4096; i += 256) {
            int k = i >> 7, n = i & 127;
            Bs[k][n] = __ldg(&B[(size_t)(kk + k) * 128 + n]);
        }
        __syncthreads();
#pragma unroll
        for (int k = 0; k < 32; k++) {
            float a0 = As[k][ty * 2 + 0];
            float a1 = As[k][ty * 2 + 1];
            const float4* bp = reinterpret_cast<const float4*>(&Bs[k][tx * 8]);
            float4 b0 = bp[0], b1 = bp[1];
            acc0[0] += a0 * b0.x; acc0[1] += a0 * b0.y; acc0[2] += a0 * b0.z; acc0[3] += a0 * b0.w;
            acc0[4] += a0 * b1.x; acc0[5] += a0 * b1.y; acc0[6] += a0 * b1.z; acc0[7] += a0 * b1.w;
            acc1[0] += a1 * b0.x; acc1[1] += a1 * b0.y; acc1[2] += a1 * b0.z; acc1[3] += a1 * b0.w;
            acc1[4] += a1 * b1.x; acc1[5] += a1 * b1.y; acc1[6] += a1 * b1.z; acc1[7] += a1 * b1.w;
        }
        __syncthreads();
    }

    const int r0 = m0 + ty * 2;
    const int c0 = tx * 8;
    float bb[8];
#pragma unroll
    for (int j = 0; j < 8; j++) bb[j] = bias ? __ldg(&bias[c0 + j]) : 0.f;
#pragma unroll
    for (int j = 0; j < 8; j++) {
        float v0 = acc0[j] + bb[j];
        float v1 = acc1[j] + bb[j];
        if (doElu) {
            v0 = v0 > 0.f ? v0 : expm1f(v0);
            v1 = v1 > 0.f ? v1 : expm1f(v1);
        }
        acc0[j] = v0; acc1[j] = v1;
    }
    float4* o0 = reinterpret_cast<float4*>(&C[(size_t)r0 * 128 + c0]);
    float4* o1 = reinterpret_cast<float4*>(&C[(size_t)(r0 + 1) * 128 + c0]);
    o0[0] = make_float4(acc0[0], acc0[1], acc0[2], acc0[3]);
    o0[1] = make_float4(acc0[4], acc0[5], acc0[6], acc0[7]);
    o1[0] = make_float4(acc1[0], acc1[1], acc1[2], acc1[3]);
    o1[1] = make_float4(acc1[4], acc1[5], acc1[6], acc1[7]);
}

// ---------------- cross: per-edge 128-d dot -> logits (no atomics) ----------------
__global__ void cross_dot(const int* __restrict__ src, const int* __restrict__ dst,
                          const float* __restrict__ Xa, const float* __restrict__ Xb,
                          float* __restrict__ logits, int E)
{
    int e = (blockIdx.x * blockDim.x + threadIdx.x) >> 5;
    int lane = threadIdx.x & 31;
    if (e >= E) return;
    int s = __ldg(&src[e]), t = __ldg(&dst[e]);
    float4 a = __ldg(reinterpret_cast<const float4*>(Xa) + (size_t)s * 32 + lane);
    float4 b = __ldg(reinterpret_cast<const float4*>(Xb) + (size_t)t * 32 + lane);
    float d = a.x * b.x + a.y * b.y + a.z * b.z + a.w * b.w;
#pragma unroll
    for (int off = 16; off > 0; off >>= 1) d += __shfl_down_sync(0xffffffffu, d, off);
    if (lane == 0) logits[e] = d;
}

// ---------------- cross gather: warp/node, softmax over incoming edges, aggregate V[src] ----------------
__global__ void cross_gather(const int* __restrict__ start, const int* __restrict__ eid,
                             const int* __restrict__ src, const float* __restrict__ logits,
                             const float* __restrict__ V, float* __restrict__ out, int N)
{
    int n = (blockIdx.x * blockDim.x + threadIdx.x) >> 5;
    int lane = threadIdx.x & 31;
    if (n >= N) return;
    int s0 = __ldg(&start[n]), s1 = __ldg(&start[n + 1]);
    float4* o = reinterpret_cast<float4*>(out) + (size_t)n * 32 + lane;
    if (s0 == s1) { *o = make_float4(0.f, 0.f, 0.f, 0.f); return; }

    float m = -INFINITY;
    for (int i = s0 + lane; i < s1; i += 32)
        m = fmaxf(m, __ldg(&logits[__ldg(&eid[i])]));
#pragma unroll
    for (int off = 16; off > 0; off >>= 1) m = fmaxf(m, __shfl_xor_sync(0xffffffffu, m, off));

    float sum = 0.f;
    float4 acc = make_float4(0.f, 0.f, 0.f, 0.f);
    for (int i = s0; i < s1; i++) {
        int e = __ldg(&eid[i]);
        int s = __ldg(&src[e]);
        float w = expf(__ldg(&logits[e]) - m);
        sum += w;
        float4 v = __ldg(reinterpret_cast<const float4*>(V) + (size_t)s * 32 + lane);
        acc.x += w * v.x; acc.y += w * v.y; acc.z += w * v.z; acc.w += w * v.w;
    }
    float inv = 1.f / sum;
    *o = make_float4(acc.x * inv, acc.y * inv, acc.z * inv, acc.w * inv);
}

// ---------------- intra gather: softmax weights depend only on sA[src] (segment-const part cancels) ----------------
__global__ void intra_gather(const int* __restrict__ start, const int* __restrict__ eid,
                             const int* __restrict__ src, const float* __restrict__ sA,
                             const float* __restrict__ V1, const float* __restrict__ V2b,
                             float* __restrict__ out, int N)
{
    int n = (blockIdx.x * blockDim.x + threadIdx.x) >> 5;
    int lane = threadIdx.x & 31;
    if (n >= N) return;
    int s0 = __ldg(&start[n]), s1 = __ldg(&start[n + 1]);
    float4* o = reinterpret_cast<float4*>(out) + (size_t)n * 32 + lane;
    if (s0 == s1) { *o = make_float4(0.f, 0.f, 0.f, 0.f); return; }

    float m = -INFINITY;
    for (int i = s0 + lane; i < s1; i += 32)
        m = fmaxf(m, __ldg(&sA[__ldg(&src[__ldg(&eid[i])])]));
#pragma unroll
    for (int off = 16; off > 0; off >>= 1) m = fmaxf(m, __shfl_xor_sync(0xffffffffu, m, off));

    float sum = 0.f;
    float4 acc = make_float4(0.f, 0.f, 0.f, 0.f);
    for (int i = s0; i < s1; i++) {
        int e = __ldg(&eid[i]);
        int s = __ldg(&src[e]);
        float w = expf(__ldg(&sA[s]) - m);
        sum += w;
        float4 v = __ldg(reinterpret_cast<const float4*>(V1) + (size_t)s * 32 + lane);
        acc.x += w * v.x; acc.y += w * v.y; acc.z += w * v.z; acc.w += w * v.w;
    }
    float inv = 1.f / sum;
    float4 v2 = __ldg(reinterpret_cast<const float4*>(V2b) + (size_t)n * 32 + lane);
    *o = make_float4(acc.x * inv + v2.x, acc.y * inv + v2.y,
                     acc.z * inv + v2.z, acc.w * inv + v2.w);
}

// ---------------- Xt2q shortcut: masked copy by cross src-degree ----------------
__global__ void mask_copy(const float* __restrict__ X, const int* __restrict__ deg,
                          float* __restrict__ out, int N)
{
    int i = blockIdx.x * blockDim.x + threadIdx.x;
    if (i >= N * 128) return;
    out[i] = (__ldg(&deg[i >> 7]) > 0) ? X[i] : 0.f;
}

// ---------------- per-node scalar dot sA = X . W[0:128] ----------------
__global__ void node_scalar(const float* __restrict__ X, const float* __restrict__ Wa,
                            float* __restrict__ sA, int N)
{
    int n = (blockIdx.x * blockDim.x + threadIdx.x) >> 5;
    int lane = threadIdx.x & 31;
    if (n >= N) return;
    float4 x  = __ldg(reinterpret_cast<const float4*>(X) + (size_t)n * 32 + lane);
    float4 wa = __ldg(reinterpret_cast<const float4*>(Wa) + lane);
    float dA = x.x * wa.x + x.y * wa.y + x.z * wa.z + x.w * wa.w;
#pragma unroll
    for (int off = 16; off > 0; off >>= 1) dA += __shfl_down_sync(0xffffffffu, dA, off);
    if (lane == 0) sA[n] = dA;
}

// ---------------- column mean of X[M,128] into out[128] (pre-zeroed) ----------------
__global__ void colmean_kernel(const float* __restrict__ X, float* __restrict__ out, int M)
{
    __shared__ float s[256];
    int c = threadIdx.x & 127;
    int half = threadIdx.x >> 7;
    float acc = 0.f;
    for (int r = blockIdx.x * 2 + half; r < M; r += gridDim.x * 2)
        acc += X[(size_t)r * 128 + c];
    s[threadIdx.x] = acc;
    __syncthreads();
    if (half == 0) atomicAdd(&out[c], (s[c] + s[c + 128]) * (1.0f / (float)M));
}

// ---------------- fold Q-mean block of W_mt into bias ----------------
__global__ void bmt_eff_kernel(const float* __restrict__ qmean, const float* __restrict__ W_mt,
                               const float* __restrict__ b_mt, float* __restrict__ beff)
{
    int j = threadIdx.x;            // 0..127
    float acc = __ldg(&b_mt[j]);
    for (int k = 0; k < 128; k++)
        acc += qmean[k] * __ldg(&W_mt[(size_t)(256 + k) * 128 + j]);
    beff[j] = acc;
}

// ---------------- flag select: if only_run_inter, output the merged features ----------------
__global__ void flag_select(const int* __restrict__ flag, const float* __restrict__ merged,
                            float* __restrict__ out, int n)
{
    int i = blockIdx.x * blockDim.x + threadIdx.x;
    if (i >= n) return;
    if (*flag) out[i] = merged[i];
}

// ============================================================================
extern "C" void kernel_launch(void* const* d_in, const int* in_sizes, int n_in,
                              void* d_out, int out_size)
{
    const float* Xq        = (const float*)d_in[0];
    const int*   eiq       = (const int*)  d_in[1];
    const float* Xt        = (const float*)d_in[2];
    const int*   eit       = (const int*)  d_in[3];
    const int*   cr_src    = (const int*)  d_in[6];
    const int*   cr_dst    = (const int*)  d_in[7];
    const int*   flag      = (const int*)  d_in[9];
    const float* W_ac_q    = (const float*)d_in[10]; const float* b_ac_q = (const float*)d_in[11];
    const float* W_ac_t    = (const float*)d_in[12]; const float* b_ac_t = (const float*)d_in[13];
    const float* W_vc_q    = (const float*)d_in[14]; const float* b_vc_q = (const float*)d_in[15];
    const float* W_vc_t    = (const float*)d_in[16]; const float* b_vc_t = (const float*)d_in[17];
    const float* W_mq      = (const float*)d_in[18]; const float* b_mq   = (const float*)d_in[19];
    const float* W_mt      = (const float*)d_in[20]; const float* b_mt   = (const float*)d_in[21];
    const float* W_aq      = (const float*)d_in[22];
    const float* W_vq      = (const float*)d_in[24]; const float* b_vq   = (const float*)d_in[25];
    const float* W_at      = (const float*)d_in[26];
    const float* W_vt      = (const float*)d_in[28]; const float* b_vt   = (const float*)d_in[29];

    const int nq = in_sizes[0] / DD;
    const int nt = in_sizes[2] / DD;
    const int ec = in_sizes[6];
    const int eq = in_sizes[1] / 2;
    const int et = in_sizes[3] / 2;

    float *Xq_ac, *Xt_ac, *Xq_vc, *Xt_vc, *Xq2t, *Xt2q, *Xq_m, *Xt_m;
    float *V1q, *V2q, *V1t, *V2t, *logits, *sAt, *sAq, *qmean, *bmt;
    int *count, *start, *cursor, *eid, *degsrc;
    cudaGetSymbolAddress((void**)&Xq_ac, g_Xq_ac);
    cudaGetSymbolAddress((void**)&Xt_ac, g_Xt_ac);
    cudaGetSymbolAddress((void**)&Xq_vc, g_Xq_vc);
    cudaGetSymbolAddress((void**)&Xt_vc, g_Xt_vc);
    cudaGetSymbolAddress((void**)&Xq2t,  g_Xq2t);
    cudaGetSymbolAddress((void**)&Xt2q,  g_Xt2q);
    cudaGetSymbolAddress((void**)&Xq_m,  g_Xq_m);
    cudaGetSymbolAddress((void**)&Xt_m,  g_Xt_m);
    cudaGetSymbolAddress((void**)&V1q,   g_V1q);
    cudaGetSymbolAddress((void**)&V2q,   g_V2q);
    cudaGetSymbolAddress((void**)&V1t,   g_V1t);
    cudaGetSymbolAddress((void**)&V2t,   g_V2t);
    cudaGetSymbolAddress((void**)&logits,g_logits);
    cudaGetSymbolAddress((void**)&sAt,   g_sAt);
    cudaGetSymbolAddress((void**)&sAq,   g_sAq);
    cudaGetSymbolAddress((void**)&qmean, g_qmean);
    cudaGetSymbolAddress((void**)&bmt,   g_bmt);
    cudaGetSymbolAddress((void**)&count, g_count);
    cudaGetSymbolAddress((void**)&start, g_start);
    cudaGetSymbolAddress((void**)&cursor,g_cursor);
    cudaGetSymbolAddress((void**)&eid,   g_eid);
    cudaGetSymbolAddress((void**)&degsrc,g_degsrc);

    float* out_q = (float*)d_out;
    float* out_t = (float*)d_out + (size_t)nq * DD;

    const int T = 256;
#define FILLI(p, v, n) filli_kernel<<<((n) + T - 1) / T, T>>>((p), (v), (n))
#define FILLF(p, v, n) fillf_kernel<<<((n) + T - 1) / T, T>>>((p), (v), (n))
#define CSR_BUILD(idxptr, Ecnt, Nn)                                             \
    do {                                                                        \
        FILLI(count, 0, (Nn) + 1);                                              \
        count_kernel<<<((Ecnt) + T - 1) / T, T>>>((idxptr), count, (Ecnt));     \
        scan_kernel<<<1, SCAN_T>>>(count, start, cursor, (Nn));                 \
        fill_kernel<<<((Ecnt) + T - 1) / T, T>>>((idxptr), cursor, eid, (Ecnt));\
    } while (0)

    // 1) elu projections
    gemm2_kernel<<<(nq + 31) / 32, 256>>>(Xq, Xq, DD, 0, W_ac_q, b_ac_q, Xq_ac, 1, nq);
    gemm2_kernel<<<(nt + 31) / 32, 256>>>(Xt, Xt, DD, 0, W_ac_t, b_ac_t, Xt_ac, 1, nt);
    gemm2_kernel<<<(nq + 31) / 32, 256>>>(Xq, Xq, DD, 0, W_vc_q, b_vc_q, Xq_vc, 1, nq);
    gemm2_kernel<<<(nt + 31) / 32, 256>>>(Xt, Xt, DD, 0, W_vc_t, b_vc_t, Xt_vc, 1, nt);

    // 2) cross attention: logits, src-degree (mask), CSR by dst, gather into Xq2t
    cross_dot<<<(ec + 7) / 8, 256>>>(cr_src, cr_dst, Xq_ac, Xt_ac, logits, ec);
    FILLI(degsrc, 0, nq);
    count_kernel<<<(ec + T - 1) / T, T>>>(cr_src, degsrc, ec);
    CSR_BUILD(cr_dst, ec, nt);
    cross_gather<<<(nt * 32 + T - 1) / T, T>>>(start, eid, cr_src, logits, Xq_vc, Xq2t, nt);
    mask_copy<<<(nq * DD + T - 1) / T, T>>>(Xt_vc, degsrc, Xt2q, nq);

    // 3) Q-mean folded bias for W_mt
    FILLF(qmean, 0.f, DD);
    colmean_kernel<<<64, 256>>>(Xq, qmean, nq);
    bmt_eff_kernel<<<1, 128>>>(qmean, W_mt, b_mt, bmt);

    // 4) merge GEMMs
    gemm2_kernel<<<(nq + 31) / 32, 256>>>(Xq, Xt2q, DD, DD, W_mq, b_mq, Xq_m, 0, nq);
    gemm2_kernel<<<(nt + 31) / 32, 256>>>(Xt, Xq2t, DD, DD, W_mt, bmt, Xt_m, 0, nt);

    // 5) intra precompute (src-side attention scalar + value projections)
    node_scalar<<<(nt * 32 + T - 1) / T, T>>>(Xt_m, W_at, sAt, nt);
    node_scalar<<<(nq * 32 + T - 1) / T, T>>>(Xq_m, W_aq, sAq, nq);
    gemm2_kernel<<<(nt + 31) / 32, 256>>>(Xt_m, Xt_m, DD, 0, W_vt,             nullptr, V1t, 0, nt);
    gemm2_kernel<<<(nt + 31) / 32, 256>>>(Xt_m, Xt_m, DD, 0, W_vt + 128 * 128, b_vt,    V2t, 0, nt);
    gemm2_kernel<<<(nq + 31) / 32, 256>>>(Xq_m, Xq_m, DD, 0, W_vq,             nullptr, V1q, 0, nq);
    gemm2_kernel<<<(nq + 31) / 32, 256>>>(Xq_m, Xq_m, DD, 0, W_vq + 128 * 128, b_vq,    V2q, 0, nq);

    // 6) intra t-graph: CSR by dst + fused softmax-gather (writes out_t directly)
    CSR_BUILD(eit + et, et, nt);
    intra_gather<<<(nt * 32 + T - 1) / T, T>>>(start, eid, eit, sAt, V1t, V2t, out_t, nt);

    // 7) intra q-graph
    CSR_BUILD(eiq + eq, eq, nq);
    intra_gather<<<(nq * 32 + T - 1) / T, T>>>(start, eid, eiq, sAq, V1q, V2q, out_q, nq);

    // 8) only_run_inter: overwrite with merged features
    flag_select<<<(nq * DD + T - 1) / T, T>>>(flag, Xq_m, out_q, nq * DD);
    flag_select<<<(nt * DD + T - 1) / T, T>>>(flag, Xt_m, out_t, nt * DD);
#undef FILLI
#undef FILLF
#undef CSR_BUILD
}